// round 9
// baseline (speedup 1.0000x reference)
#include <cuda_runtime.h>
#include <cuda_bf16.h>
#include <cstdint>

#define NUM_TREES 20
#define FD        128
#define NNODES    31
#define NPAD      32
#define NLEAVES   32
#define BM        128

// smem strides (padded for bank-conflict-free fragment access)
#define A_STRIDE_W   68      // words per A row (136 bf16 = 272B; 4-bank shift/row)
#define B_STRIDE_W   68      // words per B row
#define D_STRIDE_F   40      // floats per D row (160B; 8-bank shift/row)

// smem layout (bytes)
#define SM_A      0                           // 128*272      = 34816
#define SM_B0     (SM_A + 128*272)            // 32*272       =  8704
#define SM_B1     (SM_B0 + 32*272)
#define SM_D      (SM_B1 + 32*272)            // 128*160      = 20480
#define SM_LCP    (SM_D + 128*160)            // 20*64*4      =  5120
#define SM_BIAS   (SM_LCP + 5120)             // 20*31*4      =  2480
#define SMEM_BYTES (SM_BIAS + 2480 + 16)

// ---------------- device-global scratch (no allocation allowed) ----------------
__device__ __align__(16) __nv_bfloat16 g_Wm[NUM_TREES * NPAD * FD]; // masked weights bf16, [t][n][k]
__device__ float g_lcp[NUM_TREES * NLEAVES * 2];                    // softmax(leaf)*softmax(tree_w)

// ---------------- helpers ----------------
__device__ __forceinline__ uint32_t pack_bf16x2(float lo, float hi) {
    uint32_t r;
    asm("cvt.rn.bf16x2.f32 %0, %1, %2;" : "=r"(r) : "f"(hi), "f"(lo));
    return r;
}

// D = A(16x16 row) * B(16x8 col) + D, bf16 in / f32 acc  — plain sm_80 PTX, valid on sm_103
__device__ __forceinline__ void mma16816(float* d, const uint32_t* a, const uint32_t* b) {
    asm volatile(
        "mma.sync.aligned.m16n8k16.row.col.f32.bf16.bf16.f32 "
        "{%0,%1,%2,%3}, {%4,%5,%6,%7}, {%8,%9}, {%0,%1,%2,%3};"
        : "+f"(d[0]), "+f"(d[1]), "+f"(d[2]), "+f"(d[3])
        : "r"(a[0]), "r"(a[1]), "r"(a[2]), "r"(a[3]), "r"(b[0]), "r"(b[1]));
}

// ---------------- prep kernels ----------------
__global__ void prep_scalar(const float* __restrict__ leaf_logits,
                            const float* __restrict__ tree_weights) {
    __shared__ float tw[NUM_TREES];
    int tid = threadIdx.x;
    if (tid == 0) {
        float m = -1e30f;
        for (int t = 0; t < NUM_TREES; t++) m = fmaxf(m, tree_weights[t]);
        float e[NUM_TREES], s = 0.f;
        for (int t = 0; t < NUM_TREES; t++) { e[t] = expf(tree_weights[t] - m); s += e[t]; }
        float inv = 1.f / s;
        for (int t = 0; t < NUM_TREES; t++) tw[t] = e[t] * inv;
    }
    __syncthreads();
    for (int i = tid; i < NUM_TREES * NLEAVES; i += blockDim.x) {
        int t = i / NLEAVES;
        float a = leaf_logits[2 * i], b = leaf_logits[2 * i + 1];
        float m = fmaxf(a, b);
        float ea = expf(a - m), eb = expf(b - m);
        float inv = tw[t] / (ea + eb);
        g_lcp[2 * i]     = ea * inv;
        g_lcp[2 * i + 1] = eb * inv;
    }
}

__global__ void prep_w(const float* __restrict__ sw, const float* __restrict__ fm) {
    int i = blockIdx.x * blockDim.x + threadIdx.x;
    if (i >= NUM_TREES * NPAD * FD) return;
    int t = i / (NPAD * FD);
    int r = i % (NPAD * FD);
    int n = r / FD, f = r % FD;
    float v = 0.f;
    if (n < NNODES) v = sw[(t * NNODES + n) * FD + f] * fm[t * FD + f];
    g_Wm[i] = __float2bfloat16(v);
}

// ---------------- main fused kernel ----------------
__global__ __launch_bounds__(128, 2)
void nrf_main(const float* __restrict__ x, const float* __restrict__ bias,
              float* __restrict__ out) {
    extern __shared__ char sm[];
    const int tid  = threadIdx.x;
    const int wid  = tid >> 5;
    const int lane = tid & 31;

    // ---- stage A tile: 128 rows x 128 f32 -> bf16, coalesced, padded rows ----
    {
        const float4* xg = reinterpret_cast<const float4*>(x) + (size_t)blockIdx.x * (BM * 32);
#pragma unroll
        for (int i = 0; i < 32; i++) {
            int idx  = i * 128 + tid;          // float4 index within tile
            float4 v = xg[idx];
            int row  = idx >> 5;               // 32 float4 per row
            int ch   = idx & 31;
            uint2 p  = make_uint2(pack_bf16x2(v.x, v.y), pack_bf16x2(v.z, v.w));
            *reinterpret_cast<uint2*>(sm + SM_A + row * 272 + ch * 8) = p;
        }
    }
    // ---- stage lcp + bias + first B slab ----
    float* lcp_s  = reinterpret_cast<float*>(sm + SM_LCP);
    float* bias_s = reinterpret_cast<float*>(sm + SM_BIAS);
    for (int i = tid; i < NUM_TREES * NLEAVES * 2; i += 128) lcp_s[i]  = g_lcp[i];
    for (int i = tid; i < NUM_TREES * NNODES;      i += 128) bias_s[i] = bias[i];
    {
        const uint4* src = reinterpret_cast<const uint4*>(g_Wm);   // tree 0
#pragma unroll
        for (int j = 0; j < 4; j++) {
            int c = tid * 4 + j;                       // 512 x 16B chunks
            uint4 v = src[c];
            int n = c >> 4, kc = c & 15;               // 16 chunks per 256B k-row
            *reinterpret_cast<uint4*>(sm + SM_B0 + n * 272 + kc * 16) = v;
        }
    }
    __syncthreads();

    const uint32_t* Aw = reinterpret_cast<const uint32_t*>(sm + SM_A);
    float* Ds = reinterpret_cast<float*>(sm + SM_D);

    float acc0 = 0.f, acc1 = 0.f;

    for (int t = 0; t < NUM_TREES; t++) {
        const uint32_t* Bw = reinterpret_cast<const uint32_t*>(
            sm + ((t & 1) ? SM_B1 : SM_B0));

        // prefetch next tree's B slab into registers (overlaps MMA)
        uint4 nb[4];
        if (t + 1 < NUM_TREES) {
            const uint4* src = reinterpret_cast<const uint4*>(g_Wm) + (t + 1) * 512;
#pragma unroll
            for (int j = 0; j < 4; j++) nb[j] = src[tid * 4 + j];
        }

        // ---- GEMM: this warp's 32 rows x 32 nodes x K=128 ----
        float d[2][4][4];
#pragma unroll
        for (int mi = 0; mi < 2; mi++)
#pragma unroll
            for (int ni = 0; ni < 4; ni++)
#pragma unroll
                for (int c = 0; c < 4; c++) d[mi][ni][c] = 0.f;

#pragma unroll
        for (int ki = 0; ki < 8; ki++) {
            const int kw = ki * 8 + (lane & 3);
            uint32_t bf[4][2];
#pragma unroll
            for (int ni = 0; ni < 4; ni++) {
                const uint32_t* bp = Bw + (ni * 8 + (lane >> 2)) * B_STRIDE_W + kw;
                bf[ni][0] = bp[0];
                bf[ni][1] = bp[4];
            }
            uint32_t a[2][4];
#pragma unroll
            for (int mi = 0; mi < 2; mi++) {
                const int r = wid * 32 + mi * 16 + (lane >> 2);
                const uint32_t* ap = Aw + r * A_STRIDE_W + kw;
                a[mi][0] = ap[0];
                a[mi][1] = ap[8 * A_STRIDE_W];
                a[mi][2] = ap[4];
                a[mi][3] = ap[8 * A_STRIDE_W + 4];
            }
#pragma unroll
            for (int mi = 0; mi < 2; mi++)
#pragma unroll
                for (int ni = 0; ni < 4; ni++)
                    mma16816(d[mi][ni], a[mi], bf[ni]);
        }

        // commit prefetched B to the other buffer
        if (t + 1 < NUM_TREES) {
#pragma unroll
            for (int j = 0; j < 4; j++) {
                int c = tid * 4 + j;
                int n = c >> 4, kc = c & 15;
                *reinterpret_cast<uint4*>(
                    sm + (((t + 1) & 1) ? SM_B1 : SM_B0) + n * 272 + kc * 16) = nb[j];
            }
        }

        // ---- transpose D fragments through smem (warp-private rows) ----
#pragma unroll
        for (int mi = 0; mi < 2; mi++) {
            const int r   = wid * 32 + mi * 16 + (lane >> 2);
            const int col = (lane & 3) * 2;
#pragma unroll
            for (int ni = 0; ni < 4; ni++) {
                *reinterpret_cast<float2*>(Ds + r * D_STRIDE_F + ni * 8 + col) =
                    make_float2(d[mi][ni][0], d[mi][ni][1]);
                *reinterpret_cast<float2*>(Ds + (r + 8) * D_STRIDE_F + ni * 8 + col) =
                    make_float2(d[mi][ni][2], d[mi][ni][3]);
            }
        }
        __syncwarp();

        // ---- epilogue: lane owns batch row wid*32+lane; 31 node logits resident ----
        {
            const float* myrow = Ds + (wid * 32 + lane) * D_STRIDE_F;
            const float* bs    = bias_s + t * NNODES;
            float sg[NNODES];
#pragma unroll
            for (int n = 0; n < NNODES; n++) {
                float z = myrow[n] + bs[n];
                sg[n] = __fdividef(1.0f, 1.0f + __expf(-z));   // 2 MUFU
            }
            // heap descent: right child multiplies g, left multiplies 1-g
            float l1[2];
            l1[0] = 1.f - sg[0]; l1[1] = sg[0];
            float l2[4];
#pragma unroll
            for (int i = 0; i < 2; i++) { float g = sg[1 + i];  l2[2*i] = l1[i]*(1.f-g); l2[2*i+1] = l1[i]*g; }
            float l3[8];
#pragma unroll
            for (int i = 0; i < 4; i++) { float g = sg[3 + i];  l3[2*i] = l2[i]*(1.f-g); l3[2*i+1] = l2[i]*g; }
            float l4[16];
#pragma unroll
            for (int i = 0; i < 8; i++) { float g = sg[7 + i];  l4[2*i] = l3[i]*(1.f-g); l4[2*i+1] = l3[i]*g; }
            const float* lc = lcp_s + t * (NLEAVES * 2);
#pragma unroll
            for (int i = 0; i < 16; i++) {
                float g   = sg[15 + i];
                float lp1 = l4[i] * g;
                float lp0 = l4[i] - lp1;
                acc0 += lp0 * lc[4*i + 0] + lp1 * lc[4*i + 2];
                acc1 += lp0 * lc[4*i + 1] + lp1 * lc[4*i + 3];
            }
        }
        __syncwarp();      // D reads complete before next tree overwrites
        __syncthreads();   // B double-buffer handoff
    }

    const size_t row_g = (size_t)blockIdx.x * BM + wid * 32 + lane;
    *reinterpret_cast<float2*>(out + row_g * 2) = make_float2(acc0, acc1);
}

// ---------------- launch ----------------
extern "C" void kernel_launch(void* const* d_in, const int* in_sizes, int n_in,
                              void* d_out, int out_size) {
    const float* x  = (const float*)d_in[0];   // [131072,128]
    const float* sw = (const float*)d_in[1];   // [20,31,128]
    const float* sb = (const float*)d_in[2];   // [20,31]
    const float* ll = (const float*)d_in[3];   // [20,32,2]
    const float* tw = (const float*)d_in[4];   // [20]
    const float* fm = (const float*)d_in[5];   // [20,128]
    float* out = (float*)d_out;                // [131072,2]

    prep_scalar<<<1, 256>>>(ll, tw);
    prep_w<<<(NUM_TREES * NPAD * FD + 255) / 256, 256>>>(sw, fm);

    static bool attr_set = false;
    if (!attr_set) {
        cudaFuncSetAttribute(nrf_main, cudaFuncAttributeMaxDynamicSharedMemorySize, SMEM_BYTES);
        attr_set = true;
    }
    nrf_main<<<131072 / BM, 128, SMEM_BYTES>>>(x, sb, out);
}

// round 13
// speedup vs baseline: 1.0089x; 1.0089x over previous
#include <cuda_runtime.h>
#include <cuda_bf16.h>
#include <cstdint>

#define NUM_TREES 20
#define FD        128
#define NNODES    31
#define NPAD      32
#define NLEAVES   32
#define BM        128

// smem strides
#define A_STRIDE_B   272     // bytes per A row (128 bf16 + 8 pad chunks) -> LDSM conflict-free
#define B_STRIDE_B   272
#define D_STRIDE_F   40      // floats per D row

// smem layout (bytes)
#define SM_A      0                       // 128*272 = 34816
#define SM_B0     34816                   // 32*272  =  8704
#define SM_B1     43520
#define SM_D      52224                   // 128*160 = 20480
#define SM_LCP    72704                   // 20*64*4 =  5120
#define SM_BIAS   77824                   // 20*31*4 =  2480
#define SMEM_BYTES 80320

// ---------------- device-global scratch ----------------
__device__ __align__(16) __nv_bfloat16 g_Wm[NUM_TREES * NPAD * FD]; // masked weights bf16 [t][n][k]
__device__ float g_lcp[NUM_TREES * NLEAVES * 2];                    // softmax(leaf)*softmax(tree_w)

// ---------------- helpers ----------------
__device__ __forceinline__ uint32_t smem_u32(const void* p) {
    uint32_t a;
    asm("{ .reg .u64 t; cvta.to.shared.u64 t, %1; cvt.u32.u64 %0, t; }" : "=r"(a) : "l"(p));
    return a;
}
__device__ __forceinline__ uint32_t pack_bf16x2(float lo, float hi) {
    uint32_t r;
    asm("cvt.rn.bf16x2.f32 %0, %1, %2;" : "=r"(r) : "f"(hi), "f"(lo));
    return r;
}
__device__ __forceinline__ void ldsm4(uint32_t* r, uint32_t addr) {
    asm volatile("ldmatrix.sync.aligned.m8n8.x4.shared.b16 {%0,%1,%2,%3}, [%4];"
                 : "=r"(r[0]), "=r"(r[1]), "=r"(r[2]), "=r"(r[3]) : "r"(addr));
}
__device__ __forceinline__ void ldsm2(uint32_t* r, uint32_t addr) {
    asm volatile("ldmatrix.sync.aligned.m8n8.x2.shared.b16 {%0,%1}, [%2];"
                 : "=r"(r[0]), "=r"(r[1]) : "r"(addr));
}
__device__ __forceinline__ void mma16816(float* d, const uint32_t* a, const uint32_t* b) {
    asm volatile(
        "mma.sync.aligned.m16n8k16.row.col.f32.bf16.bf16.f32 "
        "{%0,%1,%2,%3}, {%4,%5,%6,%7}, {%8,%9}, {%0,%1,%2,%3};"
        : "+f"(d[0]), "+f"(d[1]), "+f"(d[2]), "+f"(d[3])
        : "r"(a[0]), "r"(a[1]), "r"(a[2]), "r"(a[3]), "r"(b[0]), "r"(b[1]));
}
__device__ __forceinline__ float sigm(float z) {
    float t;
    asm("tanh.approx.f32 %0, %1;" : "=f"(t) : "f"(z * 0.5f));
    return fmaf(t, 0.5f, 0.5f);              // 1 MUFU + 2 FMA
}

// ---------------- fused prep kernel ----------------
__global__ void prep(const float* __restrict__ sw, const float* __restrict__ fm,
                     const float* __restrict__ ll, const float* __restrict__ tw) {
    int b = blockIdx.x, tid = threadIdx.x;
    if (b < 320) {                                   // masked bf16 weights
        int i = b * 256 + tid;                       // exactly 81920 = 320*256
        int t = i / (NPAD * FD);
        int r = i % (NPAD * FD);
        int n = r / FD, f = r % FD;
        float v = 0.f;
        if (n < NNODES) v = sw[(t * NNODES + n) * FD + f] * fm[t * FD + f];
        g_Wm[i] = __float2bfloat16(v);
    } else {                                         // lcp table, no serial section
        float m = -1e30f;
#pragma unroll
        for (int t = 0; t < NUM_TREES; t++) m = fmaxf(m, tw[t]);
        float e[NUM_TREES], s = 0.f;
#pragma unroll
        for (int t = 0; t < NUM_TREES; t++) { e[t] = __expf(tw[t] - m); s += e[t]; }
        float invs = 1.f / s;
        for (int i = tid; i < NUM_TREES * NLEAVES; i += 256) {
            int t = i / NLEAVES;
            float a = ll[2 * i], c = ll[2 * i + 1];
            float mm = fmaxf(a, c);
            float ea = __expf(a - mm), eb = __expf(c - mm);
            float inv = (e[t] * invs) / (ea + eb);
            g_lcp[2 * i]     = ea * inv;
            g_lcp[2 * i + 1] = eb * inv;
        }
    }
}

// ---------------- main fused kernel ----------------
__global__ __launch_bounds__(256, 2)
void nrf_main(const float* __restrict__ x, const float* __restrict__ bias,
              float* __restrict__ out) {
    extern __shared__ char sm[];
    const uint32_t sb = smem_u32(sm);
    const int tid  = threadIdx.x;
    const int wid  = tid >> 5;
    const int lane = tid & 31;

    // ---- stage A tile: 128 rows x 128 f32 -> bf16 (padded rows, conflict-free) ----
    {
        const float4* xg = reinterpret_cast<const float4*>(x) + (size_t)blockIdx.x * (BM * 32);
#pragma unroll
        for (int i = 0; i < 16; i++) {
            int idx  = i * 256 + tid;          // float4 index within tile
            float4 v = xg[idx];
            int row  = idx >> 5;               // 32 float4 per row
            int ch   = idx & 31;
            uint2 p  = make_uint2(pack_bf16x2(v.x, v.y), pack_bf16x2(v.z, v.w));
            *reinterpret_cast<uint2*>(sm + SM_A + row * A_STRIDE_B + ch * 8) = p;
        }
    }
    // ---- stage lcp + bias + first B slab ----
    float* lcp_s  = reinterpret_cast<float*>(sm + SM_LCP);
    float* bias_s = reinterpret_cast<float*>(sm + SM_BIAS);
    for (int i = tid; i < NUM_TREES * NLEAVES * 2; i += 256) lcp_s[i]  = g_lcp[i];
    for (int i = tid; i < NUM_TREES * NNODES;      i += 256) bias_s[i] = bias[i];
    {
        const uint4* src = reinterpret_cast<const uint4*>(g_Wm);   // tree 0
#pragma unroll
        for (int j = 0; j < 2; j++) {
            int c = tid * 2 + j;                       // 512 x 16B chunks
            uint4 v = src[c];
            *reinterpret_cast<uint4*>(sm + SM_B0 + (c >> 4) * B_STRIDE_B + (c & 15) * 16) = v;
        }
    }
    __syncthreads();

    float* Ds = reinterpret_cast<float*>(sm + SM_D);
    // ldmatrix base addresses
    const uint32_t a_base = sb + SM_A + (wid * 16 + (lane & 15)) * A_STRIDE_B + (lane >> 4) * 16;
    const uint32_t b_off  = (lane & 7) * B_STRIDE_B + ((lane >> 3) & 1) * 16;

    float acc0 = 0.f, acc1 = 0.f;
    const int  row_l = tid >> 1;           // epilogue: 2 threads per row
    const int  h     = tid & 1;            // subtree half

    for (int t = 0; t < NUM_TREES; t++) {
        const uint32_t bcur = sb + ((t & 1) ? SM_B1 : SM_B0) + b_off;

        // prefetch next tree's B slab into registers (overlaps MMA)
        uint4 nb[2];
        if (t + 1 < NUM_TREES) {
            const uint4* src = reinterpret_cast<const uint4*>(g_Wm) + (t + 1) * 512;
#pragma unroll
            for (int j = 0; j < 2; j++) nb[j] = src[tid * 2 + j];
        }

        // ---- GEMM: this warp's 16 rows x 32 nodes x K=128 ----
        float d[4][4];
#pragma unroll
        for (int ni = 0; ni < 4; ni++)
#pragma unroll
            for (int c = 0; c < 4; c++) d[ni][c] = 0.f;

#pragma unroll
        for (int ki = 0; ki < 8; ki++) {
            uint32_t a[4];
            ldsm4(a, a_base + ki * 32);
#pragma unroll
            for (int ni = 0; ni < 4; ni++) {
                uint32_t b[2];
                ldsm2(b, bcur + ni * (8 * B_STRIDE_B) + ki * 32);
                mma16816(d[ni], a, b);
            }
        }

        // commit prefetched B to the other buffer
        if (t + 1 < NUM_TREES) {
            char* dst = sm + (((t + 1) & 1) ? SM_B1 : SM_B0);
#pragma unroll
            for (int j = 0; j < 2; j++) {
                int c = tid * 2 + j;
                *reinterpret_cast<uint4*>(dst + (c >> 4) * B_STRIDE_B + (c & 15) * 16) = nb[j];
            }
        }

        // ---- transpose D fragments through smem (warp-private rows) ----
        {
            const int r0 = wid * 16 + (lane >> 2);
            const int c  = (lane & 3) * 2;
#pragma unroll
            for (int ni = 0; ni < 4; ni++) {
                *reinterpret_cast<float2*>(Ds + r0 * D_STRIDE_F + ni * 8 + c) =
                    make_float2(d[ni][0], d[ni][1]);
                *reinterpret_cast<float2*>(Ds + (r0 + 8) * D_STRIDE_F + ni * 8 + c) =
                    make_float2(d[ni][2], d[ni][3]);
            }
        }
        __syncwarp();

        // ---- epilogue: thread owns (row_l, subtree h); 16 sigmoids each ----
        {
            const float* myrow = Ds + row_l * D_STRIDE_F;
            const float* bs    = bias_s + t * NNODES;
            const float* lc    = lcp_s + t * (NLEAVES * 2);

            float g0 = sigm(myrow[0] + bs[0]);
            float p  = h ? g0 : 1.f - g0;

            const int n1 = 1 + h;
            float g1 = sigm(myrow[n1] + bs[n1]);
            float m1[2];
            m1[1] = p * g1; m1[0] = p - m1[1];

            float m2[4];
#pragma unroll
            for (int i = 0; i < 2; i++) {
                int n = 3 + 2 * h + i;
                float g = sigm(myrow[n] + bs[n]);
                m2[2 * i + 1] = m1[i] * g; m2[2 * i] = m1[i] - m2[2 * i + 1];
            }
            float m3[8];
#pragma unroll
            for (int i = 0; i < 4; i++) {
                int n = 7 + 4 * h + i;
                float g = sigm(myrow[n] + bs[n]);
                m3[2 * i + 1] = m2[i] * g; m3[2 * i] = m2[i] - m3[2 * i + 1];
            }
#pragma unroll
            for (int i = 0; i < 8; i++) {
                int n = 15 + 8 * h + i;
                float g = sigm(myrow[n] + bs[n]);
                float lp1 = m3[i] * g;
                float lp0 = m3[i] - lp1;
                int j4 = 4 * (8 * h + i);
                acc0 += lp0 * lc[j4 + 0] + lp1 * lc[j4 + 2];
                acc1 += lp0 * lc[j4 + 1] + lp1 * lc[j4 + 3];
            }
        }
        __syncthreads();   // B double-buffer + D reuse handoff
    }

    // pair-combine the two subtree halves (same warp: tid, tid^1)
    float o0 = acc0 + __shfl_xor_sync(0xFFFFFFFFu, acc0, 1);
    float o1 = acc1 + __shfl_xor_sync(0xFFFFFFFFu, acc1, 1);
    if (h == 0) {
        const size_t row_g = (size_t)blockIdx.x * BM + row_l;
        *reinterpret_cast<float2*>(out + row_g * 2) = make_float2(o0, o1);
    }
}

// ---------------- launch ----------------
extern "C" void kernel_launch(void* const* d_in, const int* in_sizes, int n_in,
                              void* d_out, int out_size) {
    const float* x  = (const float*)d_in[0];   // [131072,128]
    const float* sw = (const float*)d_in[1];   // [20,31,128]
    const float* sb = (const float*)d_in[2];   // [20,31]
    const float* ll = (const float*)d_in[3];   // [20,32,2]
    const float* tw = (const float*)d_in[4];   // [20]
    const float* fm = (const float*)d_in[5];   // [20,128]
    float* out = (float*)d_out;                // [131072,2]

    prep<<<321, 256>>>(sw, fm, ll, tw);

    static bool attr_set = false;
    if (!attr_set) {
        cudaFuncSetAttribute(nrf_main, cudaFuncAttributeMaxDynamicSharedMemorySize, SMEM_BYTES);
        attr_set = true;
    }
    nrf_main<<<131072 / BM, 256, SMEM_BYTES>>>(x, sb, out);
}

// round 14
// speedup vs baseline: 1.1572x; 1.1469x over previous
#include <cuda_runtime.h>
#include <cuda_bf16.h>
#include <cstdint>

#define NUM_TREES 20
#define FD        128
#define NNODES    31
#define NPAD      32
#define NLEAVES   32
#define BM        128

#define A_STRIDE_B 272          // bytes per A row (ldsm conflict-free: 16B shift/row)
#define B_STRIDE_B 272
#define D_STRIDE_W 33           // words per D row (odd -> conflict-free scalar access)

// smem: A staging (34816 B) reused as D (128*33*4 = 16896 B) after fragment load
#define SM_AD 0
#define SM_B0 34816
#define SM_B1 43520
#define SMEM_BYTES 52224

// ---------------- device-global scratch ----------------
// B slabs stored PRE-PADDED: per tree 8704 B = 32 rows x 272 B (272-byte row stride)
__device__ __align__(16) __nv_bfloat16 g_WmP[NUM_TREES * NPAD * (A_STRIDE_B / 2)];
__device__ float g_q[NUM_TREES * NLEAVES];        // w_t * softmax(leaf)[class 0]

__constant__ float c_q[NUM_TREES * NLEAVES];      // 2560 B
__constant__ float c_bias[NUM_TREES * NNODES];    // 2480 B

// ---------------- helpers ----------------
__device__ __forceinline__ uint32_t smem_u32(const void* p) {
    uint32_t a;
    asm("{ .reg .u64 t; cvta.to.shared.u64 t, %1; cvt.u32.u64 %0, t; }" : "=r"(a) : "l"(p));
    return a;
}
__device__ __forceinline__ uint32_t pack_bf16x2(float lo, float hi) {
    uint32_t r;
    asm("cvt.rn.bf16x2.f32 %0, %1, %2;" : "=r"(r) : "f"(hi), "f"(lo));
    return r;
}
__device__ __forceinline__ void ldsm4(uint32_t* r, uint32_t addr) {
    asm volatile("ldmatrix.sync.aligned.m8n8.x4.shared.b16 {%0,%1,%2,%3}, [%4];"
                 : "=r"(r[0]), "=r"(r[1]), "=r"(r[2]), "=r"(r[3]) : "r"(addr));
}
__device__ __forceinline__ void mma16816(float* d, const uint32_t* a, const uint32_t* b) {
    asm volatile(
        "mma.sync.aligned.m16n8k16.row.col.f32.bf16.bf16.f32 "
        "{%0,%1,%2,%3}, {%4,%5,%6,%7}, {%8,%9}, {%0,%1,%2,%3};"
        : "+f"(d[0]), "+f"(d[1]), "+f"(d[2]), "+f"(d[3])
        : "r"(a[0]), "r"(a[1]), "r"(a[2]), "r"(a[3]), "r"(b[0]), "r"(b[1]));
}
__device__ __forceinline__ float sigm(float z) {
    float t;
    asm("tanh.approx.f32 %0, %1;" : "=f"(t) : "f"(z * 0.5f));
    return fmaf(t, 0.5f, 0.5f);
}

// ---------------- fused prep kernel ----------------
__global__ void prep(const float* __restrict__ sw, const float* __restrict__ fm,
                     const float* __restrict__ ll, const float* __restrict__ tw) {
    int b = blockIdx.x, tid = threadIdx.x;
    if (b < 320) {                                   // masked bf16 weights, padded layout
        int i = b * 256 + tid;                       // 81920 = 20*32*128
        int t = i / (NPAD * FD);
        int r = i % (NPAD * FD);
        int n = r / FD, f = r % FD;
        float v = 0.f;
        if (n < NNODES) v = sw[(t * NNODES + n) * FD + f] * fm[t * FD + f];
        g_WmP[(t * NPAD + n) * (A_STRIDE_B / 2) + f] = __float2bfloat16(v);
    } else {                                         // q table (class-0 x tree weight)
        float m = -1e30f;
#pragma unroll
        for (int t = 0; t < NUM_TREES; t++) m = fmaxf(m, tw[t]);
        float e[NUM_TREES], s = 0.f;
#pragma unroll
        for (int t = 0; t < NUM_TREES; t++) { e[t] = __expf(tw[t] - m); s += e[t]; }
        float invs = 1.f / s;
        for (int i = tid; i < NUM_TREES * NLEAVES; i += 256) {
            int t = i / NLEAVES;
            float a = ll[2 * i], c = ll[2 * i + 1];
            float mm = fmaxf(a, c);
            float ea = __expf(a - mm), eb = __expf(c - mm);
            g_q[i] = (e[t] * invs) * ea / (ea + eb);
        }
    }
}

// ---------------- main fused kernel ----------------
__global__ __launch_bounds__(128, 3)
void nrf_main(const float* __restrict__ x, float* __restrict__ out) {
    extern __shared__ char sm[];
    const uint32_t sb = smem_u32(sm);
    const int tid  = threadIdx.x;
    const int wid  = tid >> 5;
    const int lane = tid & 31;

    // ---- stage A tile: 128 x 128 f32 -> bf16, padded rows ----
    {
        const float4* xg = reinterpret_cast<const float4*>(x) + (size_t)blockIdx.x * (BM * 32);
#pragma unroll
        for (int i = 0; i < 32; i++) {
            int idx  = i * 128 + tid;
            float4 v = xg[idx];
            int row = idx >> 5, ch = idx & 31;
            uint2 p = make_uint2(pack_bf16x2(v.x, v.y), pack_bf16x2(v.z, v.w));
            *reinterpret_cast<uint2*>(sm + SM_AD + row * A_STRIDE_B + ch * 8) = p;
        }
    }
    // ---- stage B slab for tree 0 (linear copy, padded source) ----
    {
        const uint4* src = reinterpret_cast<const uint4*>(g_WmP);
#pragma unroll
        for (int j = 0; j < 4; j++) {
            int c = tid * 4 + j;                      // 544 x 16B chunks? no: 8704/16 = 544
            if (c < 544) *reinterpret_cast<uint4*>(sm + SM_B0 + c * 16) = src[c];
        }
        // 128 thr * 4 = 512 chunks; cover the tail 32 chunks
        int c = 512 + tid;
        if (c < 544) *reinterpret_cast<uint4*>(sm + SM_B0 + c * 16) = src[c];
    }
    __syncthreads();

    // ---- load A fragments into registers (once, reused for all 20 trees) ----
    uint32_t a[2][8][4];
    {
        const uint32_t a_base = sb + SM_AD + (wid * 32 + (lane & 15)) * A_STRIDE_B + (lane >> 4) * 16;
#pragma unroll
        for (int mi = 0; mi < 2; mi++)
#pragma unroll
            for (int ki = 0; ki < 8; ki++)
                ldsm4(a[mi][ki], a_base + mi * (16 * A_STRIDE_B) + ki * 32);
    }
    __syncthreads();     // A smem consumed; region becomes D buffer

    float* Ds = reinterpret_cast<float*>(sm + SM_AD);
    const uint32_t b_rel = (lane & 7) * B_STRIDE_B + ((lane >> 3) & 1) * 16 +
                           ((lane >> 4) & 1) * (8 * B_STRIDE_B);

    float acc0 = 0.f;

#pragma unroll 1
    for (int t = 0; t < NUM_TREES; t++) {
        // prefetch next tree's padded B slab (linear, coalesced)
        uint4 nb[4]; uint4 nbt; bool tail_pf = false;
        const bool pf = (t + 1 < NUM_TREES);
        if (pf) {
            const uint4* src = reinterpret_cast<const uint4*>(g_WmP) + (t + 1) * 544;
#pragma unroll
            for (int j = 0; j < 4; j++) nb[j] = src[tid * 4 + j];
            if (512 + tid < 544) { nbt = src[512 + tid]; tail_pf = true; }
        }

        // ---- GEMM: 32 rows x 32 nodes x K=128 per warp ----
        float d[2][4][4];
#pragma unroll
        for (int mi = 0; mi < 2; mi++)
#pragma unroll
            for (int ni = 0; ni < 4; ni++)
#pragma unroll
                for (int c = 0; c < 4; c++) d[mi][ni][c] = 0.f;

        const uint32_t bcur = sb + ((t & 1) ? SM_B1 : SM_B0) + b_rel;
#pragma unroll
        for (int ki = 0; ki < 8; ki++) {
#pragma unroll
            for (int ni2 = 0; ni2 < 2; ni2++) {
                uint32_t b4[4];
                ldsm4(b4, bcur + ni2 * (16 * B_STRIDE_B) + ki * 32);
#pragma unroll
                for (int mi = 0; mi < 2; mi++) {
                    mma16816(d[mi][ni2 * 2],     a[mi][ki], b4);
                    mma16816(d[mi][ni2 * 2 + 1], a[mi][ki], b4 + 2);
                }
            }
        }
        __syncthreads();     // all ldsm of B[cur] and all epilogue reads of D(t-1) done

        if (pf) {
            char* dst = sm + (((t + 1) & 1) ? SM_B1 : SM_B0);
#pragma unroll
            for (int j = 0; j < 4; j++)
                *reinterpret_cast<uint4*>(dst + (tid * 4 + j) * 16) = nb[j];
            if (tail_pf) *reinterpret_cast<uint4*>(dst + (512 + tid) * 16) = nbt;
        }

        // ---- D transpose store: stride-33 + rotation, fully conflict-free ----
        {
            const int r0 = wid * 32 + (lane >> 2);
            const int cq = (lane & 3) * 2;
#pragma unroll
            for (int mi = 0; mi < 2; mi++)
#pragma unroll
                for (int dd = 0; dd < 2; dd++) {
                    const int rr = r0 + mi * 16 + dd * 8;
                    float* base = Ds + rr * D_STRIDE_W;
                    const int sw4 = 4 * rr;
#pragma unroll
                    for (int ni = 0; ni < 4; ni++) {
                        const int col = ni * 8 + cq;
                        base[(col + sw4) & 31]     = d[mi][ni][dd * 2 + 0];
                        base[(col + 1 + sw4) & 31] = d[mi][ni][dd * 2 + 1];
                    }
                }
        }
        __syncwarp();        // warp-private rows: store -> load handoff

        // ---- epilogue: thread owns batch row tid; bias/q from constant port ----
        {
            const float* myrow = Ds + tid * D_STRIDE_W;
            const int sw4 = 4 * tid;
            const float* bs = c_bias + t * NNODES;
            const float* qq = c_q + t * NLEAVES;
#define LDN(n) (myrow[((n) + sw4) & 31] + bs[(n)])
            float g0 = sigm(LDN(0));
            float l1l = 1.f - g0, l1r = g0;
            float l2[4];
            { float g = sigm(LDN(1)); l2[1] = l1l * g; l2[0] = l1l - l2[1]; }
            { float g = sigm(LDN(2)); l2[3] = l1r * g; l2[2] = l1r - l2[3]; }
            float l3[8];
#pragma unroll
            for (int i = 0; i < 4; i++) {
                float g = sigm(LDN(3 + i));
                l3[2 * i + 1] = l2[i] * g; l3[2 * i] = l2[i] - l3[2 * i + 1];
            }
            float l4[16];
#pragma unroll
            for (int i = 0; i < 8; i++) {
                float g = sigm(LDN(7 + i));
                l4[2 * i + 1] = l3[i] * g; l4[2 * i] = l3[i] - l4[2 * i + 1];
            }
#pragma unroll
            for (int i = 0; i < 16; i++) {
                float g   = sigm(LDN(15 + i));
                float lp1 = l4[i] * g;
                float lp0 = l4[i] - lp1;
                acc0 += lp0 * qq[2 * i] + lp1 * qq[2 * i + 1];
            }
#undef LDN
        }
    }

    const size_t row_g = (size_t)blockIdx.x * BM + tid;
    *reinterpret_cast<float2*>(out + row_g * 2) = make_float2(acc0, 1.0f - acc0);
}

// ---------------- launch ----------------
extern "C" void kernel_launch(void* const* d_in, const int* in_sizes, int n_in,
                              void* d_out, int out_size) {
    const float* x  = (const float*)d_in[0];   // [131072,128]
    const float* sw = (const float*)d_in[1];   // [20,31,128]
    const float* sb = (const float*)d_in[2];   // [20,31]
    const float* ll = (const float*)d_in[3];   // [20,32,2]
    const float* tw = (const float*)d_in[4];   // [20]
    const float* fm = (const float*)d_in[5];   // [20,128]
    float* out = (float*)d_out;                // [131072,2]

    prep<<<321, 256>>>(sw, fm, ll, tw);

    static void* q_sym  = nullptr;
    static void* b_sym  = nullptr;
    static void* q_src  = nullptr;
    if (!q_sym) {
        cudaGetSymbolAddress(&q_sym, c_q);
        cudaGetSymbolAddress(&b_sym, c_bias);
        cudaGetSymbolAddress(&q_src, g_q);
        cudaFuncSetAttribute(nrf_main, cudaFuncAttributeMaxDynamicSharedMemorySize, SMEM_BYTES);
    }
    cudaMemcpyAsync(q_sym, q_src, NUM_TREES * NLEAVES * sizeof(float),
                    cudaMemcpyDeviceToDevice, 0);
    cudaMemcpyAsync(b_sym, sb, NUM_TREES * NNODES * sizeof(float),
                    cudaMemcpyDeviceToDevice, 0);

    nrf_main<<<131072 / BM, 128, SMEM_BYTES>>>(x, out);
}

// round 15
// speedup vs baseline: 1.3669x; 1.1812x over previous
#include <cuda_runtime.h>
#include <cuda_bf16.h>
#include <cstdint>

#define NUM_TREES 20
#define FD        128
#define NNODES    31
#define NPAD      32
#define NLEAVES   32
#define BM        128

#define A_STRIDE_B 272          // bytes per staged A row (ldsm conflict-free)
#define B_STRIDE_B 272
#define B_SLAB_B   8704         // 32 rows x 272 B
#define B_CHUNKS   544          // 16B chunks per slab

// smem: A staging + 3-slab B ring
#define SM_A  0                 // 34816 B
#define SM_B  34816
#define SMEM_BYTES (34816 + 3 * B_SLAB_B)   // 60928

// ---------------- device-global scratch ----------------
// B slabs pre-padded AND node-permuted: slab row c holds weights of node_of(c)
__device__ __align__(16) __nv_bfloat16 g_WmP[NUM_TREES * NPAD * (B_STRIDE_B / 2)];
__device__ float g_q[NUM_TREES * NLEAVES];        // w_t * softmax(leaf)[class 0]

__constant__ float c_q[NUM_TREES * NLEAVES];
__constant__ float c_bias[NUM_TREES * NNODES];

// column -> tree-node permutation (quad thread qd owns cols {8ni+2qd+par})
__host__ __device__ __forceinline__ int node_of(int ni, int par, int qd) {
    if (ni == 0) return par ? 7 + 2 * qd : 3 + qd;       // L3a / L2
    if (ni == 1) return par ? 15 + 4 * qd : 8 + 2 * qd;  // L4[0] / L3b
    if (ni == 2) return par ? 17 + 4 * qd : 16 + 4 * qd; // L4[2] / L4[1]
    return par ? (qd < 3 ? qd : -1) : 18 + 4 * qd;       // top(0,1,2)|pad / L4[3]
}

// ---------------- helpers ----------------
__device__ __forceinline__ uint32_t smem_u32(const void* p) {
    uint32_t a;
    asm("{ .reg .u64 t; cvta.to.shared.u64 t, %1; cvt.u32.u64 %0, t; }" : "=r"(a) : "l"(p));
    return a;
}
__device__ __forceinline__ uint32_t pack_bf16x2(float lo, float hi) {
    uint32_t r;
    asm("cvt.rn.bf16x2.f32 %0, %1, %2;" : "=r"(r) : "f"(hi), "f"(lo));
    return r;
}
__device__ __forceinline__ void ldsm4(uint32_t* r, uint32_t addr) {
    asm volatile("ldmatrix.sync.aligned.m8n8.x4.shared.b16 {%0,%1,%2,%3}, [%4];"
                 : "=r"(r[0]), "=r"(r[1]), "=r"(r[2]), "=r"(r[3]) : "r"(addr));
}
__device__ __forceinline__ void mma16816(float* d, const uint32_t* a, const uint32_t* b) {
    asm volatile(
        "mma.sync.aligned.m16n8k16.row.col.f32.bf16.bf16.f32 "
        "{%0,%1,%2,%3}, {%4,%5,%6,%7}, {%8,%9}, {%0,%1,%2,%3};"
        : "+f"(d[0]), "+f"(d[1]), "+f"(d[2]), "+f"(d[3])
        : "r"(a[0]), "r"(a[1]), "r"(a[2]), "r"(a[3]), "r"(b[0]), "r"(b[1]));
}
__device__ __forceinline__ float sigm(float z) {
    float t;
    asm("tanh.approx.f32 %0, %1;" : "=f"(t) : "f"(z * 0.5f));
    return fmaf(t, 0.5f, 0.5f);
}

// ---------------- fused prep kernel ----------------
__global__ void prep(const float* __restrict__ sw, const float* __restrict__ fm,
                     const float* __restrict__ ll, const float* __restrict__ tw) {
    int b = blockIdx.x, tid = threadIdx.x;
    if (b < 320) {                                   // permuted masked bf16 weights
        int i = b * 256 + tid;                       // 81920 = 20*32*128
        int t = i / (NPAD * FD);
        int r = i % (NPAD * FD);
        int c = r / FD, f = r % FD;
        int node = node_of(c >> 3, c & 1, (c & 7) >> 1);
        float v = 0.f;
        if (node >= 0) v = sw[(t * NNODES + node) * FD + f] * fm[t * FD + f];
        g_WmP[(t * NPAD + c) * (B_STRIDE_B / 2) + f] = __float2bfloat16(v);
    } else {                                         // q table (class-0 x tree weight)
        float m = -1e30f;
#pragma unroll
        for (int t = 0; t < NUM_TREES; t++) m = fmaxf(m, tw[t]);
        float e[NUM_TREES], s = 0.f;
#pragma unroll
        for (int t = 0; t < NUM_TREES; t++) { e[t] = __expf(tw[t] - m); s += e[t]; }
        float invs = 1.f / s;
        for (int i = tid; i < NUM_TREES * NLEAVES; i += 256) {
            int t = i / NLEAVES;
            float a = ll[2 * i], c = ll[2 * i + 1];
            float mm = fmaxf(a, c);
            float ea = __expf(a - mm), eb = __expf(c - mm);
            g_q[i] = (e[t] * invs) * ea / (ea + eb);
        }
    }
}

// ---------------- main fused kernel ----------------
__global__ __launch_bounds__(128, 3)
void nrf_main(const float* __restrict__ x, float* __restrict__ out) {
    extern __shared__ char sm[];
    const uint32_t sb = smem_u32(sm);
    const int tid  = threadIdx.x;
    const int wid  = tid >> 5;
    const int lane = tid & 31;
    const int qd   = lane & 3;

    // ---- stage A tile: 128 x 128 f32 -> bf16, padded rows ----
    {
        const float4* xg = reinterpret_cast<const float4*>(x) + (size_t)blockIdx.x * (BM * 32);
#pragma unroll
        for (int i = 0; i < 32; i++) {
            int idx  = i * 128 + tid;
            float4 v = xg[idx];
            int row = idx >> 5, ch = idx & 31;
            uint2 p = make_uint2(pack_bf16x2(v.x, v.y), pack_bf16x2(v.z, v.w));
            *reinterpret_cast<uint2*>(sm + SM_A + row * A_STRIDE_B + ch * 8) = p;
        }
    }
    // ---- stage B slab for tree 0 into ring slot 0 ----
    {
        const uint4* src = reinterpret_cast<const uint4*>(g_WmP);
#pragma unroll
        for (int j = 0; j < 4; j++)
            *reinterpret_cast<uint4*>(sm + SM_B + (tid * 4 + j) * 16) = src[tid * 4 + j];
        if (512 + tid < B_CHUNKS)
            *reinterpret_cast<uint4*>(sm + SM_B + (512 + tid) * 16) = src[512 + tid];
    }
    __syncthreads();

    // ---- A fragments register-resident for all 20 trees ----
    uint32_t a[2][8][4];
    {
        const uint32_t a_base = sb + SM_A + (wid * 32 + (lane & 15)) * A_STRIDE_B + (lane >> 4) * 16;
#pragma unroll
        for (int mi = 0; mi < 2; mi++)
#pragma unroll
            for (int ki = 0; ki < 8; ki++)
                ldsm4(a[mi][ki], a_base + mi * (16 * A_STRIDE_B) + ki * 32);
    }

    const uint32_t b_rel = (lane & 7) * B_STRIDE_B + ((lane >> 3) & 1) * 16 +
                           ((lane >> 4) & 1) * (8 * B_STRIDE_B);

    float acc[4] = {0.f, 0.f, 0.f, 0.f};

#pragma unroll 1
    for (int t = 0; t < NUM_TREES; t++) {
        // prefetch next tree's slab (gmem->regs; LDG latency hides under MMA)
        uint4 nb[4]; uint4 nbt;
        const bool pf = (t + 1 < NUM_TREES);
        const bool tail = (512 + tid < B_CHUNKS);
        if (pf) {
            const uint4* src = reinterpret_cast<const uint4*>(g_WmP) + (t + 1) * B_CHUNKS;
#pragma unroll
            for (int j = 0; j < 4; j++) nb[j] = src[tid * 4 + j];
            if (tail) nbt = src[512 + tid];
        }

        // bias folded into accumulator init (constant port)
        float bv[4][2];
#pragma unroll
        for (int ni = 0; ni < 4; ni++)
#pragma unroll
            for (int par = 0; par < 2; par++) {
                int node = node_of(ni, par, qd);
                bv[ni][par] = (node >= 0) ? c_bias[t * NNODES + node] : 0.f;
            }
        float d[2][4][4];
#pragma unroll
        for (int mi = 0; mi < 2; mi++)
#pragma unroll
            for (int ni = 0; ni < 4; ni++)
#pragma unroll
                for (int dd = 0; dd < 2; dd++) {
                    d[mi][ni][2 * dd + 0] = bv[ni][0];
                    d[mi][ni][2 * dd + 1] = bv[ni][1];
                }

        // ---- GEMM: 32 rows x 32 cols x K=128 per warp ----
        const uint32_t bcur = sb + SM_B + (uint32_t)(t % 3) * B_SLAB_B + b_rel;
#pragma unroll
        for (int ki = 0; ki < 8; ki++) {
#pragma unroll
            for (int ni2 = 0; ni2 < 2; ni2++) {
                uint32_t b4[4];
                ldsm4(b4, bcur + ni2 * (16 * B_STRIDE_B) + ki * 32);
#pragma unroll
                for (int mi = 0; mi < 2; mi++) {
                    mma16816(d[mi][ni2 * 2],     a[mi][ki], b4);
                    mma16816(d[mi][ni2 * 2 + 1], a[mi][ki], b4 + 2);
                }
            }
        }

        // commit prefetched slab to ring slot (t+1)%3 (last readers: iter t-2, 2 barriers old)
        if (pf) {
            char* dst = sm + SM_B + (size_t)((t + 1) % 3) * B_SLAB_B;
#pragma unroll
            for (int j = 0; j < 4; j++)
                *reinterpret_cast<uint4*>(dst + (tid * 4 + j) * 16) = nb[j];
            if (tail) *reinterpret_cast<uint4*>(dst + (512 + tid) * 16) = nbt;
        }
        __syncthreads();   // slab writes visible before next iter's ldsm

        // ---- register-resident epilogue (no smem) ----
        const float* qv = c_q + t * NLEAVES + 8 * qd;
        const int sbase = lane & ~3;
#pragma unroll
        for (int mi = 0; mi < 2; mi++)
#pragma unroll
            for (int dd = 0; dd < 2; dd++) {
                const int k = 2 * mi + dd;
                float gL2  = sigm(d[mi][0][2 * dd + 0]);
                float gL3a = sigm(d[mi][0][2 * dd + 1]);
                float gL3b = sigm(d[mi][1][2 * dd + 0]);
                float g40  = sigm(d[mi][1][2 * dd + 1]);
                float g41  = sigm(d[mi][2][2 * dd + 0]);
                float g42  = sigm(d[mi][2][2 * dd + 1]);
                float g43  = sigm(d[mi][3][2 * dd + 0]);
                float stp  = sigm(d[mi][3][2 * dd + 1]);   // top gate (node qd) or pad
                float g0 = __shfl_sync(0xFFFFFFFFu, stp, sbase + 0);
                float g1 = __shfl_sync(0xFFFFFFFFu, stp, sbase + 1);
                float g2 = __shfl_sync(0xFFFFFFFFu, stp, sbase + 2);
                float fr = (qd >= 2) ? g0 : 1.f - g0;
                float gs = (qd >= 2) ? g2 : g1;
                float f1 = (qd & 1) ? gs : 1.f - gs;
                float pt = fr * f1;
                float pB = pt * gL2, pA = pt - pB;
                float pA1 = pA * gL3a, pA0 = pA - pA1;
                float pB1 = pB * gL3b, pB0 = pB - pB1;
                float lp1, lp0;
                lp1 = pA0 * g40; lp0 = pA0 - lp1;
                acc[k] = fmaf(lp0, qv[0], fmaf(lp1, qv[1], acc[k]));
                lp1 = pA1 * g41; lp0 = pA1 - lp1;
                acc[k] = fmaf(lp0, qv[2], fmaf(lp1, qv[3], acc[k]));
                lp1 = pB0 * g42; lp0 = pB0 - lp1;
                acc[k] = fmaf(lp0, qv[4], fmaf(lp1, qv[5], acc[k]));
                lp1 = pB1 * g43; lp0 = pB1 - lp1;
                acc[k] = fmaf(lp0, qv[6], fmaf(lp1, qv[7], acc[k]));
            }
    }

    // quad butterfly: every thread gets row totals; thread qd writes row offset 8*qd
#pragma unroll
    for (int k = 0; k < 4; k++) {
        acc[k] += __shfl_xor_sync(0xFFFFFFFFu, acc[k], 1);
        acc[k] += __shfl_xor_sync(0xFFFFFFFFu, acc[k], 2);
    }
    const int r = wid * 32 + (lane >> 2) + 8 * qd;
    const size_t row_g = (size_t)blockIdx.x * BM + r;
    float a0 = acc[qd];
    *reinterpret_cast<float2*>(out + row_g * 2) = make_float2(a0, 1.0f - a0);
}

// ---------------- launch ----------------
extern "C" void kernel_launch(void* const* d_in, const int* in_sizes, int n_in,
                              void* d_out, int out_size) {
    const float* x  = (const float*)d_in[0];   // [131072,128]
    const float* sw = (const float*)d_in[1];   // [20,31,128]
    const float* sb = (const float*)d_in[2];   // [20,31]
    const float* ll = (const float*)d_in[3];   // [20,32,2]
    const float* tw = (const float*)d_in[4];   // [20]
    const float* fm = (const float*)d_in[5];   // [20,128]
    float* out = (float*)d_out;                // [131072,2]

    prep<<<321, 256>>>(sw, fm, ll, tw);

    static void* q_sym = nullptr;
    static void* b_sym = nullptr;
    static void* q_src = nullptr;
    if (!q_sym) {
        cudaGetSymbolAddress(&q_sym, c_q);
        cudaGetSymbolAddress(&b_sym, c_bias);
        cudaGetSymbolAddress(&q_src, g_q);
        cudaFuncSetAttribute(nrf_main, cudaFuncAttributeMaxDynamicSharedMemorySize, SMEM_BYTES);
    }
    cudaMemcpyAsync(q_sym, q_src, NUM_TREES * NLEAVES * sizeof(float),
                    cudaMemcpyDeviceToDevice, 0);
    cudaMemcpyAsync(b_sym, sb, NUM_TREES * NNODES * sizeof(float),
                    cudaMemcpyDeviceToDevice, 0);

    nrf_main<<<131072 / BM, 128, SMEM_BYTES>>>(x, out);
}